// round 5
// baseline (speedup 1.0000x reference)
#include <cuda_runtime.h>
#include <cuda_bf16.h>
#include <math.h>
#include <stdint.h>

// Problem constants
#define DDIM 1024
#define NEXP 8
#define HDIM 4096
#define TOPK 2
#define NTOK 8192               // B*S
#define NROWS (NTOK * TOPK)     // 16384

// Fast-path GEMM tile: 128(M) x 64(N) x 32(K), static smem, single buffer
#define TM 128
#define TN 64
#define TBK 32
#define A_BUF 8192              // 128 rows x 64B
#define B_BUF 4096              // 64 rows x 64B
#define SMEM_TOT (2 * A_BUF + 2 * B_BUF)   // 24576 bytes, static

// Fallback (R1-proven) tile
#define FBM 128
#define FBN 128
#define FBK 16

// ---------------- scratch (device globals; no runtime allocation) -------------
__device__ __nv_bfloat16 g_xhi[(size_t)NTOK * DDIM];
__device__ __nv_bfloat16 g_xlo[(size_t)NTOK * DDIM];
__device__ __nv_bfloat16 g_w1hi[(size_t)NEXP * HDIM * DDIM];   // [E][N=H][K=D]
__device__ __nv_bfloat16 g_w1lo[(size_t)NEXP * HDIM * DDIM];
__device__ __nv_bfloat16 g_w2hi[(size_t)NEXP * DDIM * HDIM];   // [E][N=D][K=H]
__device__ __nv_bfloat16 g_w2lo[(size_t)NEXP * DDIM * HDIM];
__device__ __nv_bfloat16 g_hhi[(size_t)NROWS * HDIM];
__device__ __nv_bfloat16 g_hlo[(size_t)NROWS * HDIM];
__device__ float g_oscr[(size_t)NROWS * DDIM];
__device__ int   g_rows_token[NROWS];
__device__ int   g_rows_dest[NROWS];
__device__ float g_wslot[NROWS];
__device__ int   g_tok_eidx[NROWS];
__device__ int   g_counts[NEXP];
__device__ int   g_offsets[NEXP + 1];
__device__ int   g_tileoff[NEXP + 1];
__device__ int   g_fill[NEXP];
__device__ int   g_flag1;   // 1 = g_hhi looks dead -> fallback GEMM1 runs
__device__ int   g_flag2;   // 1 = g_oscr looks dead -> fallback GEMM2 runs

// ---------------- helpers ------------------------------------------------------
__device__ __forceinline__ uint32_t smem_u32(const void* p) {
    return (uint32_t)__cvta_generic_to_shared(p);
}
__device__ __forceinline__ void ldmx4(uint32_t* r, uint32_t a) {
    asm volatile("ldmatrix.sync.aligned.m8n8.x4.shared.b16 {%0,%1,%2,%3}, [%4];"
                 : "=r"(r[0]), "=r"(r[1]), "=r"(r[2]), "=r"(r[3]) : "r"(a));
}
__device__ __forceinline__ void mma16816(float* d, const uint32_t* a, const uint32_t* b) {
    asm volatile(
        "mma.sync.aligned.m16n8k16.row.col.f32.bf16.bf16.f32 "
        "{%0,%1,%2,%3}, {%4,%5,%6,%7}, {%8,%9}, {%0,%1,%2,%3};"
        : "+f"(d[0]), "+f"(d[1]), "+f"(d[2]), "+f"(d[3])
        : "r"(a[0]), "r"(a[1]), "r"(a[2]), "r"(a[3]), "r"(b[0]), "r"(b[1]));
}
__device__ __forceinline__ void bsplit(float v, uint16_t& h, uint16_t& l) {
    __nv_bfloat16 hb = __float2bfloat16(v);
    __nv_bfloat16 lb = __float2bfloat16(v - __bfloat162float(hb));
    h = __bfloat16_as_ushort(hb);
    l = __bfloat16_as_ushort(lb);
}
__device__ __forceinline__ float bf_lo(uint32_t u) {
    return __bfloat162float(__ushort_as_bfloat16((unsigned short)(u & 0xFFFF)));
}
__device__ __forceinline__ float bf_hi(uint32_t u) {
    return __bfloat162float(__ushort_as_bfloat16((unsigned short)(u >> 16)));
}
__device__ __forceinline__ float gelu_exact(float v) {
    return 0.5f * v * (1.0f + erff(v * 0.70710678118654752440f));
}
// smem byte offset inside an Nx32 bf16 buffer (64B rows), 16B-chunk XOR swizzle
__device__ __forceinline__ uint32_t swz(int row, int c16) {
    return (uint32_t)(row * 64 + ((c16 ^ (row & 3)) << 4));
}

// ---------------- gating (proven in R1) ----------------------------------------
__global__ void reset_kernel() {
    int i = threadIdx.x;
    if (i < NEXP) g_counts[i] = 0;
    if (i == 0) { g_flag1 = 1; g_flag2 = 1; }
}

__global__ void gate_kernel(const float* __restrict__ x, const float* __restrict__ gw) {
    int warp = (blockIdx.x * blockDim.x + threadIdx.x) >> 5;
    int lane = threadIdx.x & 31;
    if (warp >= NTOK) return;
    const float* xr = x + (size_t)warp * DDIM;

    float acc[NEXP];
#pragma unroll
    for (int e = 0; e < NEXP; e++) acc[e] = 0.f;
    for (int d = lane; d < DDIM; d += 32) {
        float xv = xr[d];
        const float* g = gw + (size_t)d * NEXP;
#pragma unroll
        for (int e = 0; e < NEXP; e++) acc[e] = fmaf(xv, g[e], acc[e]);
    }
#pragma unroll
    for (int e = 0; e < NEXP; e++) {
#pragma unroll
        for (int o = 16; o > 0; o >>= 1)
            acc[e] += __shfl_xor_sync(0xffffffff, acc[e], o);
    }
    if (lane == 0) {
        int b0 = 0; float s0 = acc[0];
#pragma unroll
        for (int e = 1; e < NEXP; e++) if (acc[e] > s0) { s0 = acc[e]; b0 = e; }
        int b1 = -1; float s1 = -INFINITY;
#pragma unroll
        for (int e = 0; e < NEXP; e++)
            if (e != b0 && acc[e] > s1) { s1 = acc[e]; b1 = e; }
        float p = expf(s1 - s0);
        float inv = 1.0f / (1.0f + p);
        g_tok_eidx[warp * 2 + 0] = b0;
        g_tok_eidx[warp * 2 + 1] = b1;
        g_wslot[warp * 2 + 0] = inv;
        g_wslot[warp * 2 + 1] = p * inv;
        atomicAdd(&g_counts[b0], 1);
        atomicAdd(&g_counts[b1], 1);
    }
}

__global__ void scan_kernel() {
    int s = 0, ts = 0;
    for (int e = 0; e < NEXP; e++) {
        g_offsets[e] = s;
        g_tileoff[e] = ts;
        s += g_counts[e];
        ts += (g_counts[e] + TM - 1) / TM;
        g_fill[e] = 0;
    }
    g_offsets[NEXP] = s;
    g_tileoff[NEXP] = ts;
}

__global__ void build_kernel() {
    int t = blockIdx.x * blockDim.x + threadIdx.x;
    if (t >= NTOK) return;
#pragma unroll
    for (int k = 0; k < TOPK; k++) {
        int e = g_tok_eidx[t * 2 + k];
        int pos = g_offsets[e] + atomicAdd(&g_fill[e], 1);
        g_rows_token[pos] = t;
        g_rows_dest[pos] = t * 2 + k;
    }
}

// ---------------- fp32 -> bf16 hi/lo splits -----------------------------------
__global__ void split_x_kernel(const float* __restrict__ x) {
    size_t i = (size_t)blockIdx.x * blockDim.x + threadIdx.x;
    float4 v = reinterpret_cast<const float4*>(x)[i];
    float f[4] = {v.x, v.y, v.z, v.w};
    uint32_t hp[2], lp[2];
#pragma unroll
    for (int j = 0; j < 2; j++) {
        uint16_t h0, l0, h1, l1;
        bsplit(f[2 * j + 0], h0, l0);
        bsplit(f[2 * j + 1], h1, l1);
        hp[j] = (uint32_t)h0 | ((uint32_t)h1 << 16);
        lp[j] = (uint32_t)l0 | ((uint32_t)l1 << 16);
    }
    reinterpret_cast<uint2*>(g_xhi)[i] = make_uint2(hp[0], hp[1]);
    reinterpret_cast<uint2*>(g_xlo)[i] = make_uint2(lp[0], lp[1]);
}

// w [E][K][N] fp32 -> wT hi/lo [E][N][K] bf16 (transpose + split)
__global__ void split_wT_kernel(const float* __restrict__ w,
                                __nv_bfloat16* __restrict__ whi,
                                __nv_bfloat16* __restrict__ wlo,
                                int K, int N) {
    __shared__ float tile[32][33];
    int e = blockIdx.z;
    int n0 = blockIdx.x * 32, k0 = blockIdx.y * 32;
    const float* we = w + (size_t)e * K * N;
    int tx = threadIdx.x, ty = threadIdx.y;
#pragma unroll
    for (int r = ty; r < 32; r += 8)
        tile[r][tx] = we[(size_t)(k0 + r) * N + n0 + tx];
    __syncthreads();
    size_t obase = (size_t)e * N * K;
#pragma unroll
    for (int r = ty; r < 32; r += 8) {
        float v = tile[tx][r];
        uint16_t h, l;
        bsplit(v, h, l);
        size_t o = obase + (size_t)(n0 + r) * K + (k0 + tx);
        whi[o] = __ushort_as_bfloat16(h);
        wlo[o] = __ushort_as_bfloat16(l);
    }
}

// ---------------- FAST grouped GEMM via mma.sync (split-bf16, 3 passes) --------
// MODE 1: A = x (gathered hi/lo), B = w1T[e] [N=H][K=D], +b1, GELU -> g_h hi/lo
// MODE 2: A = g_h (contig rows),  B = w2T[e] [N=D][K=H], +b2 -> g_oscr[slot]
template <int MODE>
__global__ __launch_bounds__(256, 2)
void moe_gemm_mma(const float* __restrict__ bias) {
    constexpr int KDIM = (MODE == 1) ? DDIM : HDIM;
    constexpr int NDIM = (MODE == 1) ? HDIM : DDIM;
    constexpr int NCH = KDIM / TBK;

    __shared__ __align__(16) uint8_t smem[SMEM_TOT];

    int t = blockIdx.y;
    if (t >= g_tileoff[NEXP]) return;
    int e = 0;
#pragma unroll
    for (int i = 0; i < NEXP - 1; i++)
        if (t >= g_tileoff[i + 1]) e = i + 1;
    int roff = g_offsets[e];
    int cnt = g_offsets[e + 1] - roff;
    int m0 = (t - g_tileoff[e]) * TM;
    int n0 = blockIdx.x * TN;

    int tid = threadIdx.x;
    int wid = tid >> 5, lane = tid & 31;
    int wm = wid & 3, wn = wid >> 2;          // warp 32x32 tile

    const __nv_bfloat16* Ahi_g = (MODE == 1) ? g_xhi : g_hhi;
    const __nv_bfloat16* Alo_g = (MODE == 1) ? g_xlo : g_hlo;
    const __nv_bfloat16* Bhi_e = ((MODE == 1) ? g_w1hi : g_w2hi) + (size_t)e * NDIM * KDIM;
    const __nv_bfloat16* Blo_e = ((MODE == 1) ? g_w1lo : g_w2lo) + (size_t)e * NDIM * KDIM;

    // --- per-thread load geometry ------------------------------------------------
    int lc16 = tid & 3;
    int arow0 = tid >> 2;             // 0..63
    int arow1 = 64 + arow0;           // 64..127
    int src0, src1;
    if (MODE == 1) {
        src0 = (m0 + arow0 < cnt) ? g_rows_token[roff + m0 + arow0] : 0;
        src1 = (m0 + arow1 < cnt) ? g_rows_token[roff + m0 + arow1] : 0;
    } else {
        int a0g = roff + m0 + arow0, a1g = roff + m0 + arow1;
        src0 = (a0g < NROWS) ? a0g : (NROWS - 1);
        src1 = (a1g < NROWS) ? a1g : (NROWS - 1);
    }
    size_t aoff0 = (size_t)src0 * KDIM + lc16 * 8;
    size_t aoff1 = (size_t)src1 * KDIM + lc16 * 8;
    uint32_t as0 = swz(arow0, lc16), as1 = swz(arow1, lc16);
    int brow = tid >> 2;
    size_t boff = (size_t)(n0 + brow) * KDIM + lc16 * 8;
    uint32_t bs = swz(brow, lc16);

    // --- ldmatrix fragment rows ----------------------------------------------------
    int a_row[2];
#pragma unroll
    for (int mt = 0; mt < 2; mt++)
        a_row[mt] = wm * 32 + mt * 16 + ((lane >> 3) & 1) * 8 + (lane & 7);
    int a_kc = lane >> 4;
    int b_row[2];
#pragma unroll
    for (int np = 0; np < 2; np++)
        b_row[np] = wn * 32 + np * 16 + ((lane >> 4) & 1) * 8 + (lane & 7);
    int b_kc = (lane >> 3) & 1;

    float acc[2][4][4];
#pragma unroll
    for (int i = 0; i < 2; i++)
#pragma unroll
        for (int j = 0; j < 4; j++)
#pragma unroll
            for (int q = 0; q < 4; q++) acc[i][j][q] = 0.f;

    uint32_t sAh = smem_u32(smem);
    uint32_t sAl = sAh + A_BUF;
    uint32_t sBh = sAh + 2 * A_BUF;
    uint32_t sBl = sBh + B_BUF;

    // register staging (prefetch next chunk during compute)
    uint4 vAh0, vAh1, vAl0, vAl1, vBh, vBl;
    {
        int k0 = 0;
        vAh0 = *reinterpret_cast<const uint4*>(Ahi_g + aoff0 + k0);
        vAh1 = *reinterpret_cast<const uint4*>(Ahi_g + aoff1 + k0);
        vAl0 = *reinterpret_cast<const uint4*>(Alo_g + aoff0 + k0);
        vAl1 = *reinterpret_cast<const uint4*>(Alo_g + aoff1 + k0);
        vBh  = *reinterpret_cast<const uint4*>(Bhi_e + boff + k0);
        vBl  = *reinterpret_cast<const uint4*>(Blo_e + boff + k0);
    }

    for (int c = 0; c < NCH; c++) {
        __syncthreads();   // previous compute done; smem reusable
        *reinterpret_cast<uint4*>(smem + as0)                 = vAh0;
        *reinterpret_cast<uint4*>(smem + as1)                 = vAh1;
        *reinterpret_cast<uint4*>(smem + A_BUF + as0)         = vAl0;
        *reinterpret_cast<uint4*>(smem + A_BUF + as1)         = vAl1;
        *reinterpret_cast<uint4*>(smem + 2 * A_BUF + bs)      = vBh;
        *reinterpret_cast<uint4*>(smem + 2 * A_BUF + B_BUF + bs) = vBl;
        __syncthreads();

        if (c + 1 < NCH) {
            int k0 = (c + 1) * TBK;
            vAh0 = *reinterpret_cast<const uint4*>(Ahi_g + aoff0 + k0);
            vAh1 = *reinterpret_cast<const uint4*>(Ahi_g + aoff1 + k0);
            vAl0 = *reinterpret_cast<const uint4*>(Alo_g + aoff0 + k0);
            vAl1 = *reinterpret_cast<const uint4*>(Alo_g + aoff1 + k0);
            vBh  = *reinterpret_cast<const uint4*>(Bhi_e + boff + k0);
            vBl  = *reinterpret_cast<const uint4*>(Blo_e + boff + k0);
        }

#pragma unroll
        for (int k16 = 0; k16 < 2; k16++) {
            uint32_t aH[2][4], aL[2][4], bH[2][4], bL[2][4];
#pragma unroll
            for (int mt = 0; mt < 2; mt++) {
                int r = a_row[mt];
                uint32_t off = (uint32_t)(r * 64 + (((k16 * 2 + a_kc) ^ (r & 3)) << 4));
                ldmx4(aH[mt], sAh + off);
                ldmx4(aL[mt], sAl + off);
            }
#pragma unroll
            for (int np = 0; np < 2; np++) {
                int r = b_row[np];
                uint32_t off = (uint32_t)(r * 64 + (((k16 * 2 + b_kc) ^ (r & 3)) << 4));
                ldmx4(bH[np], sBh + off);
                ldmx4(bL[np], sBl + off);
            }
#pragma unroll
            for (int mt = 0; mt < 2; mt++)
#pragma unroll
                for (int ng = 0; ng < 4; ng++) {
                    mma16816(acc[mt][ng], aH[mt], &bH[ng >> 1][(ng & 1) * 2]);
                    mma16816(acc[mt][ng], aH[mt], &bL[ng >> 1][(ng & 1) * 2]);
                    mma16816(acc[mt][ng], aL[mt], &bH[ng >> 1][(ng & 1) * 2]);
                }
        }
    }

    // --- epilogue ------------------------------------------------------------------
    const float* be = bias + (size_t)e * NDIM;
    int tr = lane >> 2;
    int tc = (lane & 3) * 2;
#pragma unroll
    for (int mt = 0; mt < 2; mt++) {
#pragma unroll
        for (int half = 0; half < 2; half++) {
            int row = wm * 32 + mt * 16 + half * 8 + tr;
            int r = m0 + row;
            if (r >= cnt) continue;
            size_t drow;
            if (MODE == 1) drow = (size_t)(roff + r) * NDIM;
            else drow = (size_t)g_rows_dest[roff + r] * NDIM;
#pragma unroll
            for (int ng = 0; ng < 4; ng++) {
                int col = n0 + wn * 32 + ng * 8 + tc;
                float v0 = acc[mt][ng][half * 2 + 0] + be[col];
                float v1 = acc[mt][ng][half * 2 + 1] + be[col + 1];
                if (MODE == 1) {
                    v0 = gelu_exact(v0);
                    v1 = gelu_exact(v1);
                    uint16_t h0, l0, h1, l1;
                    bsplit(v0, h0, l0);
                    bsplit(v1, h1, l1);
                    *reinterpret_cast<uint32_t*>(g_hhi + drow + col) =
                        (uint32_t)h0 | ((uint32_t)h1 << 16);
                    *reinterpret_cast<uint32_t*>(g_hlo + drow + col) =
                        (uint32_t)l0 | ((uint32_t)l1 << 16);
                } else {
                    *reinterpret_cast<float2*>(g_oscr + drow + col) = make_float2(v0, v1);
                }
            }
        }
    }
}

// ---------------- check kernels -------------------------------------------------
__global__ void check_h_kernel() {
    size_t idx = ((size_t)blockIdx.x * blockDim.x + threadIdx.x) * 8192;
    if (idx < (size_t)NROWS * HDIM) {
        if (__bfloat16_as_ushort(g_hhi[idx]) != 0) g_flag1 = 0;
    }
}
__global__ void check_o_kernel() {
    size_t idx = ((size_t)blockIdx.x * blockDim.x + threadIdx.x) * 2048;
    if (idx < (size_t)NROWS * DDIM) {
        if (g_oscr[idx] != 0.0f) g_flag2 = 0;
    }
}

// ---------------- FALLBACK SIMT GEMMs (R1-proven structure) ---------------------
// fb MODE 1: A = x fp32 gathered, B = w1 [E][D][H], +b1, GELU -> bsplit -> g_h hi/lo
// fb MODE 2: A = g_hhi+g_hlo,     B = w2 [E][H][D], +b2 -> g_oscr[slot]
template <int MODE>
__global__ __launch_bounds__(256)
void fb_gemm(const float* __restrict__ Aparam,
             const float* __restrict__ Bmat,
             const float* __restrict__ bias) {
    if ((MODE == 1 ? g_flag1 : g_flag2) == 0) return;   // fast path succeeded

    constexpr int KDIM = (MODE == 1) ? DDIM : HDIM;
    constexpr int NDIM = (MODE == 1) ? HDIM : DDIM;

    int e = blockIdx.z;
    int roff = g_offsets[e];
    int cnt = g_offsets[e + 1] - roff;
    int m0 = blockIdx.y * FBM;
    if (m0 >= cnt) return;
    int n0 = blockIdx.x * FBN;

    const float* Bexp = Bmat + (size_t)e * KDIM * NDIM;
    const float* bexp = bias + (size_t)e * NDIM;

    __shared__ float As[FBK][FBM];
    __shared__ float Bs[FBK][FBN];
    __shared__ int rowsrc[FBM];

    int tid = threadIdx.x;
    if (tid < FBM) {
        int r = m0 + tid;
        int src = -1;
        if (r < cnt) src = (MODE == 1) ? g_rows_token[roff + r] : (roff + r);
        rowsrc[tid] = src;
    }
    __syncthreads();

    float acc[8][8];
#pragma unroll
    for (int i = 0; i < 8; i++)
#pragma unroll
        for (int j = 0; j < 8; j++) acc[i][j] = 0.f;

    int ty = tid >> 4, tx = tid & 15;

    for (int k0 = 0; k0 < KDIM; k0 += FBK) {
#pragma unroll
        for (int p = 0; p < 2; p++) {
            int row = (tid >> 2) + p * 64;
            int c4 = (tid & 3) * 4;
            int src = rowsrc[row];
            float f0 = 0.f, f1 = 0.f, f2 = 0.f, f3 = 0.f;
            if (src >= 0) {
                if (MODE == 1) {
                    float4 v = *reinterpret_cast<const float4*>(
                        Aparam + (size_t)src * KDIM + k0 + c4);
                    f0 = v.x; f1 = v.y; f2 = v.z; f3 = v.w;
                } else {
                    uint2 vh = *reinterpret_cast<const uint2*>(g_hhi + (size_t)src * KDIM + k0 + c4);
                    uint2 vl = *reinterpret_cast<const uint2*>(g_hlo + (size_t)src * KDIM + k0 + c4);
                    f0 = bf_lo(vh.x) + bf_lo(vl.x);
                    f1 = bf_hi(vh.x) + bf_hi(vl.x);
                    f2 = bf_lo(vh.y) + bf_lo(vl.y);
                    f3 = bf_hi(vh.y) + bf_hi(vl.y);
                }
            }
            As[c4 + 0][row] = f0;
            As[c4 + 1][row] = f1;
            As[c4 + 2][row] = f2;
            As[c4 + 3][row] = f3;
        }
#pragma unroll
        for (int p = 0; p < 2; p++) {
            int brow2 = (tid >> 5) + p * 8;
            int bc = (tid & 31) * 4;
            float4 v = *reinterpret_cast<const float4*>(
                Bexp + (size_t)(k0 + brow2) * NDIM + n0 + bc);
            *reinterpret_cast<float4*>(&Bs[brow2][bc]) = v;
        }
        __syncthreads();

#pragma unroll
        for (int kk = 0; kk < FBK; kk++) {
            float a[8], b[8];
#pragma unroll
            for (int i = 0; i < 8; i++) a[i] = As[kk][ty * 8 + i];
#pragma unroll
            for (int j = 0; j < 8; j++) b[j] = Bs[kk][tx * 8 + j];
#pragma unroll
            for (int i = 0; i < 8; i++)
#pragma unroll
                for (int j = 0; j < 8; j++)
                    acc[i][j] = fmaf(a[i], b[j], acc[i][j]);
        }
        __syncthreads();
    }

#pragma unroll
    for (int i = 0; i < 8; i++) {
        int r = m0 + ty * 8 + i;
        if (r >= cnt) continue;
#pragma unroll
        for (int j = 0; j < 8; j++) {
            int col = n0 + tx * 8 + j;
            float v = acc[i][j] + bexp[col];
            if (MODE == 1) {
                v = gelu_exact(v);
                uint16_t h, l;
                bsplit(v, h, l);
                size_t o = (size_t)(roff + r) * NDIM + col;
                g_hhi[o] = __ushort_as_bfloat16(h);
                g_hlo[o] = __ushort_as_bfloat16(l);
            } else {
                int slot = g_rows_dest[roff + r];
                g_oscr[(size_t)slot * NDIM + col] = v;
            }
        }
    }
}

// ---------------- combine ------------------------------------------------------
__global__ void combine_kernel(float* __restrict__ y) {
    int idx = blockIdx.x * blockDim.x + threadIdx.x;
    if (idx >= NTOK * DDIM) return;
    int t = idx >> 10;
    int d = idx & (DDIM - 1);
    float w0 = g_wslot[t * 2 + 0];
    float w1 = g_wslot[t * 2 + 1];
    float v0 = g_oscr[(size_t)(t * 2 + 0) * DDIM + d];
    float v1 = g_oscr[(size_t)(t * 2 + 1) * DDIM + d];
    y[idx] = fmaf(w0, v0, w1 * v1);
}

// ---------------- launch -------------------------------------------------------
extern "C" void kernel_launch(void* const* d_in, const int* in_sizes, int n_in,
                              void* d_out, int out_size) {
    const float* x  = (const float*)d_in[0];  // [B,S,D]
    const float* gw = (const float*)d_in[1];  // [D,E]
    const float* w1 = (const float*)d_in[2];  // [E,D,H]
    const float* b1 = (const float*)d_in[3];  // [E,H]
    const float* w2 = (const float*)d_in[4];  // [E,H,D]
    const float* b2 = (const float*)d_in[5];  // [E,D]
    float* y = (float*)d_out;

    reset_kernel<<<1, 32>>>();
    gate_kernel<<<NTOK / 8, 256>>>(x, gw);
    scan_kernel<<<1, 1>>>();
    build_kernel<<<NTOK / 256, 256>>>();

    split_x_kernel<<<(NTOK * DDIM / 4) / 256, 256>>>(x);
    split_wT_kernel<<<dim3(HDIM / 32, DDIM / 32, NEXP), dim3(32, 8)>>>(w1, g_w1hi, g_w1lo, DDIM, HDIM);
    split_wT_kernel<<<dim3(DDIM / 32, HDIM / 32, NEXP), dim3(32, 8)>>>(w2, g_w2hi, g_w2lo, HDIM, DDIM);

    int ntiles = NROWS / TM + NEXP;   // upper bound on total m-tiles

    // fast GEMM1 + self-check + fallback
    moe_gemm_mma<1><<<dim3(HDIM / TN, ntiles, 1), 256>>>(b1);
    check_h_kernel<<<32, 256>>>();
    fb_gemm<1><<<dim3(HDIM / FBN, NROWS / FBM, NEXP), 256>>>(x, w1, b1);

    // fast GEMM2 + self-check + fallback
    moe_gemm_mma<2><<<dim3(DDIM / TN, ntiles, 1), 256>>>(b2);
    check_o_kernel<<<32, 256>>>();
    fb_gemm<2><<<dim3(DDIM / FBN, NROWS / FBM, NEXP), 256>>>(nullptr, w2, b2);

    combine_kernel<<<(NTOK * DDIM) / 256, 256>>>(y);
}